// round 16
// baseline (speedup 1.0000x reference)
#include <cuda_runtime.h>
#include <cuda_bf16.h>
#include <math.h>
#include <stdint.h>

// Problem constants
#define BB   2
#define SEQ  2048
#define DMODEL 1024
#define NH   16
#define DH   64
#define BH   (BB*NH)          // 32
#define MTOT (BB*SEQ)         // 4096

#define OUT_ELEMS  ((size_t)MTOT * DMODEL)          // 4,194,304
#define ATTN_ELEMS ((size_t)BH * SEQ * SEQ)         // 134,217,728

typedef unsigned long long u64;

// ===========================================================================
// HMMA m16n8k16 bf16 (portable PTX, works on compute_103 virtual arch)
// Fragment layouts (verified by the passing R15 GEMM):
//   A row-major 16x16: a0=A[g][2cc..+1] a1=A[g+8][..] a2=A[g][2cc+8..] a3=A[g+8][..]
//   B col-major 16x8 stored smem[n][k]: b0=B[n=g][2cc..+1] b1=B[n=g][2cc+8..]
//   C: c0,c1=C[g][2cc..+1]; c2,c3=C[g+8][2cc..+1]
// ===========================================================================
__device__ __forceinline__ void mma_bf16(float* c, const uint32_t* a, const uint32_t* b) {
    asm volatile(
        "mma.sync.aligned.m16n8k16.row.col.f32.bf16.bf16.f32 "
        "{%0,%1,%2,%3}, {%4,%5,%6,%7}, {%8,%9}, {%0,%1,%2,%3};"
        : "+f"(c[0]), "+f"(c[1]), "+f"(c[2]), "+f"(c[3])
        : "r"(a[0]), "r"(a[1]), "r"(a[2]), "r"(a[3]), "r"(b[0]), "r"(b[1]));
}

// bf16 split/pack helpers
__device__ __forceinline__ uint32_t pack_hi2(float a, float b, float& ra, float& rb) {
    __nv_bfloat16 ha = __float2bfloat16(a), hb = __float2bfloat16(b);
    ra = a - __bfloat162float(ha); rb = b - __bfloat162float(hb);
    __nv_bfloat162 p = __halves2bfloat162(ha, hb);
    return *reinterpret_cast<uint32_t*>(&p);
}
__device__ __forceinline__ uint32_t pack_bf2(float a, float b) {
    __nv_bfloat162 p = __floats2bfloat162_rn(a, b);
    return *reinterpret_cast<uint32_t*>(&p);
}

// ===========================================================================
// Scratch
// ===========================================================================
__device__ float g_coef[MTOT * DMODEL];
__device__ __nv_bfloat16 g_Qhi[BH * SEQ * DH];   // [b,h,s,d]
__device__ __nv_bfloat16 g_Qlo[BH * SEQ * DH];
__device__ __nv_bfloat16 g_Khi[BH * SEQ * DH];   // [b,h,s,d]
__device__ __nv_bfloat16 g_Klo[BH * SEQ * DH];
__device__ __nv_bfloat16 g_Vthi[BH * DH * SEQ];  // [b,h,d,s]  (transposed)
__device__ __nv_bfloat16 g_Vtlo[BH * DH * SEQ];
__device__ float g_ctx[BH * SEQ * DH];
__device__ float g_rowsum[BH * SEQ];
__device__ float g_Pbuf[ATTN_ELEMS];
__device__ int   g_mask_kind;   // 0=u8, 1=i32, 2=f32
__device__ __nv_bfloat16 g_Whi[5 * DMODEL * DMODEL];
__device__ __nv_bfloat16 g_Wlo[5 * DMODEL * DMODEL];

// ===========================================================================
// Mask dtype detector
// ===========================================================================
__global__ void detect_mask_kind_k(const unsigned char* __restrict__ m) {
    __shared__ int odd1, f3;
    if (threadIdx.x == 0) { odd1 = 0; f3 = 0; }
    __syncthreads();
    int lo = 0, lf = 0;
    for (int i = threadIdx.x; i < 4096; i += blockDim.x) {
        unsigned char b = m[i];
        if ((i & 3) != 0 && b == 1)    lo = 1;
        if ((i & 3) == 3 && b == 0x3F) lf = 1;
    }
    if (lo) atomicOr(&odd1, 1);
    if (lf) atomicOr(&f3, 1);
    __syncthreads();
    if (threadIdx.x == 0) g_mask_kind = odd1 ? 0 : (f3 ? 2 : 1);
}

// ===========================================================================
// Weight prep: transpose fp32 W [K,N] -> bf16 hi/lo [N,K]
// ===========================================================================
__global__ void __launch_bounds__(256) wconv_k(
    const float* __restrict__ W,
    __nv_bfloat16* __restrict__ hiT, __nv_bfloat16* __restrict__ loT)
{
    __shared__ float t[32][33];
    const int n0 = blockIdx.x * 32, k0 = blockIdx.y * 32;
    const int tx = threadIdx.x & 31, ty = threadIdx.x >> 5;
    #pragma unroll
    for (int i = 0; i < 4; i++) {
        int kk = ty + i * 8;
        t[kk][tx] = W[(size_t)(k0 + kk) * DMODEL + n0 + tx];
    }
    __syncthreads();
    #pragma unroll
    for (int i = 0; i < 4; i++) {
        int nn = ty + i * 8;
        float x = t[tx][nn];
        __nv_bfloat16 h = __float2bfloat16(x);
        float r = x - __bfloat162float(h);
        size_t o = (size_t)(n0 + nn) * DMODEL + k0 + tx;
        hiT[o] = h;
        loT[o] = __float2bfloat16(r);
    }
}

// ===========================================================================
// HMMA bf16-split GEMM: 128x128 per CTA, 256 thr, 8 warps (2m x 4n),
// warp tile 64x32, K chunked by 64.  D = Ahi*Bhi + Ahi*Blo + Alo*Bhi.
// MODE 0: coef = 1 + sigmoid(A@W + bias)            -> C fp32 [m][n]
// MODE 1: (A@W) * coef                              -> Chi/Clo bf16 [b,h,s,d]
// MODE 2: plain projection                          -> Chi/Clo bf16 [b,h,d,s] (transposed)
// MODE 3: A from [b,h,s,d]; C = A@W + residual      -> C fp32 [m][n]
// ===========================================================================
#define SMB_STRIDE 36
#define SM_ARR (128 * SMB_STRIDE)
#define SM_TOTAL (4 * SM_ARR * 4)   // 73728 bytes

template<int MODE>
__global__ void __launch_bounds__(256) gemm_hmma_k(
    const float* __restrict__ A,
    const __nv_bfloat16* __restrict__ BhiT, const __nv_bfloat16* __restrict__ BloT,
    const float* __restrict__ aux, float* __restrict__ C,
    __nv_bfloat16* __restrict__ Chi, __nv_bfloat16* __restrict__ Clo)
{
    extern __shared__ uint32_t sm[];
    uint32_t* sAhi = sm;
    uint32_t* sAlo = sAhi + SM_ARR;
    uint32_t* sBhi = sAlo + SM_ARR;
    uint32_t* sBlo = sBhi + SM_ARR;

    const int tid = threadIdx.x;
    const int m0 = blockIdx.y * 128, n0 = blockIdx.x * 128;
    const int wid = tid >> 5, lane = tid & 31;
    const int wm = (wid & 1) * 64, wn = (wid >> 1) * 32;
    const int g = lane >> 2, cc = lane & 3;

    const int row  = tid >> 1;
    const int kseg = (tid & 1) * 32;

    float acc[4][4][4] = {};

    for (int ch = 0; ch < 16; ch++) {
        const int k0 = ch * 64;

        float4 a[8];
        if (MODE == 3) {
            int m = m0 + row;
            int b = m >> 11, s = m & (SEQ - 1);
            int h = k0 >> 6;
            const float* src = &A[(((size_t)(b * NH + h)) * SEQ + s) * DH + kseg];
            #pragma unroll
            for (int q = 0; q < 8; q++) a[q] = *(const float4*)&src[q * 4];
        } else {
            const float* src = &A[(size_t)(m0 + row) * DMODEL + k0 + kseg];
            #pragma unroll
            for (int q = 0; q < 8; q++) a[q] = *(const float4*)&src[q * 4];
        }
        uint4 bh4[4], bl4[4];
        {
            const size_t bo = (size_t)(n0 + row) * DMODEL + k0 + kseg;
            #pragma unroll
            for (int q = 0; q < 4; q++) {
                bh4[q] = *(const uint4*)&BhiT[bo + q * 8];
                bl4[q] = *(const uint4*)&BloT[bo + q * 8];
            }
        }

        __syncthreads();

        #pragma unroll
        for (int q = 0; q < 4; q++) {
            float4 f0 = a[q * 2], f1 = a[q * 2 + 1];
            float r0, r1, r2, r3, r4, r5, r6, r7;
            uint4 hi4, lo4;
            hi4.x = pack_hi2(f0.x, f0.y, r0, r1);
            hi4.y = pack_hi2(f0.z, f0.w, r2, r3);
            hi4.z = pack_hi2(f1.x, f1.y, r4, r5);
            hi4.w = pack_hi2(f1.z, f1.w, r6, r7);
            lo4.x = pack_bf2(r0, r1); lo4.y = pack_bf2(r2, r3);
            lo4.z = pack_bf2(r4, r5); lo4.w = pack_bf2(r6, r7);
            int off = row * SMB_STRIDE + (kseg >> 1) + q * 4;
            *(uint4*)&sAhi[off] = hi4;
            *(uint4*)&sAlo[off] = lo4;
            *(uint4*)&sBhi[off] = bh4[q];
            *(uint4*)&sBlo[off] = bl4[q];
        }
        __syncthreads();

        #pragma unroll
        for (int kc = 0; kc < 4; kc++) {
            uint32_t ah[4][4], al[4][4];
            #pragma unroll
            for (int mt = 0; mt < 4; mt++) {
                int i0 = (wm + mt * 16 + g) * SMB_STRIDE + kc * 8 + cc;
                int i1 = i0 + 8 * SMB_STRIDE;
                ah[mt][0] = sAhi[i0];     ah[mt][1] = sAhi[i1];
                ah[mt][2] = sAhi[i0 + 4]; ah[mt][3] = sAhi[i1 + 4];
                al[mt][0] = sAlo[i0];     al[mt][1] = sAlo[i1];
                al[mt][2] = sAlo[i0 + 4]; al[mt][3] = sAlo[i1 + 4];
            }
            #pragma unroll
            for (int nt = 0; nt < 4; nt++) {
                int bi = (wn + nt * 8 + g) * SMB_STRIDE + kc * 8 + cc;
                uint32_t bh[2] = { sBhi[bi], sBhi[bi + 4] };
                uint32_t bl[2] = { sBlo[bi], sBlo[bi + 4] };
                #pragma unroll
                for (int mt = 0; mt < 4; mt++) {
                    mma_bf16(acc[mt][nt], ah[mt], bh);
                    mma_bf16(acc[mt][nt], ah[mt], bl);
                    mma_bf16(acc[mt][nt], al[mt], bh);
                }
            }
        }
    }

    auto epi = [&](int m, int n, float2 v) {
        if (MODE == 0) {
            float2 bb = *(const float2*)&aux[n];
            v.x = 1.0f + 1.0f / (1.0f + __expf(-(v.x + bb.x)));
            v.y = 1.0f + 1.0f / (1.0f + __expf(-(v.y + bb.y)));
            *(float2*)&C[(size_t)m * DMODEL + n] = v;
        } else if (MODE == 1) {
            float2 cf = *(const float2*)&aux[(size_t)m * DMODEL + n];
            v.x *= cf.x; v.y *= cf.y;
            int b = m >> 11, s = m & (SEQ - 1);
            int h = n >> 6, d = n & 63;
            float r0, r1;
            uint32_t hi = pack_hi2(v.x, v.y, r0, r1);
            uint32_t lo = pack_bf2(r0, r1);
            size_t o = (((size_t)(b * NH + h)) * SEQ + s) * DH + d;
            *(uint32_t*)&Chi[o] = hi;
            *(uint32_t*)&Clo[o] = lo;
        } else if (MODE == 2) {
            int b = m >> 11, s = m & (SEQ - 1);
            int h = n >> 6, d = n & 63;
            size_t o0 = (((size_t)(b * NH + h)) * DH + d) * SEQ + s;
            __nv_bfloat16 h0 = __float2bfloat16(v.x);
            __nv_bfloat16 h1 = __float2bfloat16(v.y);
            Chi[o0]       = h0;
            Chi[o0 + SEQ] = h1;
            Clo[o0]       = __float2bfloat16(v.x - __bfloat162float(h0));
            Clo[o0 + SEQ] = __float2bfloat16(v.y - __bfloat162float(h1));
        } else {
            float2 r = *(const float2*)&aux[(size_t)m * DMODEL + n];
            v.x += r.x; v.y += r.y;
            *(float2*)&C[(size_t)m * DMODEL + n] = v;
        }
    };

    #pragma unroll
    for (int mt = 0; mt < 4; mt++) {
        #pragma unroll
        for (int nt = 0; nt < 4; nt++) {
            int m = m0 + wm + mt * 16 + g;
            int n = n0 + wn + nt * 8 + 2 * cc;
            epi(m,     n, make_float2(acc[mt][nt][0], acc[mt][nt][1]));
            epi(m + 8, n, make_float2(acc[mt][nt][2], acc[mt][nt][3]));
        }
    }
}

// ===========================================================================
// HMMA scores: per CTA 128 s-rows x all 2048 t; tile 128x128, K-dim=64.
// P = exp(mask ? -inf : dist * (Q.K)/8) unnormalized; rowsums to global.
// ===========================================================================
#define SC_SMEM (4 * SM_ARR * 4)   // 73728

__global__ void __launch_bounds__(256) attn_scores_hmma_k(
    const __nv_bfloat16* __restrict__ Qhi, const __nv_bfloat16* __restrict__ Qlo,
    const __nv_bfloat16* __restrict__ Khi, const __nv_bfloat16* __restrict__ Klo,
    const float* __restrict__ dist, const void* __restrict__ mask,
    float* __restrict__ P, float* __restrict__ rowsum)
{
    extern __shared__ uint32_t sm[];
    uint32_t* sQh = sm;
    uint32_t* sQl = sQh + SM_ARR;
    uint32_t* sKh = sQl + SM_ARR;
    uint32_t* sKl = sKh + SM_ARR;
    __shared__ float srow[128];

    const int tid = threadIdx.x;
    const int h = blockIdx.x, st = blockIdx.y, b = blockIdx.z;
    const int bh = b * NH + h;
    const int s0 = st * 128;
    const int kind = g_mask_kind;
    const int wid = tid >> 5, lane = tid & 31;
    const int wm = (wid & 1) * 64, wn = (wid >> 1) * 32;
    const int g = lane >> 2, cc = lane & 3;

    if (tid < 128) srow[tid] = 0.0f;

    // Q tile once: 128 rows x 64 bf16 (2 threads/row)
    {
        const int row = tid >> 1, seg = (tid & 1) * 16;   // b32 offset
        const size_t qo = ((size_t)bh * SEQ + s0 + row) * DH + (tid & 1) * 32;
        const uint4* qh = (const uint4*)&Qhi[qo];
        const uint4* ql = (const uint4*)&Qlo[qo];
        #pragma unroll
        for (int q = 0; q < 4; q++) {
            *(uint4*)&sQh[row * SMB_STRIDE + seg + q * 4] = qh[q];
            *(uint4*)&sQl[row * SMB_STRIDE + seg + q * 4] = ql[q];
        }
    }

    float rowacc[8] = {};
    const unsigned char* m8 = (const unsigned char*)mask;
    const int*           mi = (const int*)mask;
    const float*         mf = (const float*)mask;

    for (int t0 = 0; t0 < SEQ; t0 += 128) {
        // K tile
        const int row = tid >> 1, seg = (tid & 1) * 16;
        uint4 kh[4], kl[4];
        {
            const size_t ko = ((size_t)bh * SEQ + t0 + row) * DH + (tid & 1) * 32;
            const uint4* khp = (const uint4*)&Khi[ko];
            const uint4* klp = (const uint4*)&Klo[ko];
            #pragma unroll
            for (int q = 0; q < 4; q++) { kh[q] = khp[q]; kl[q] = klp[q]; }
        }
        __syncthreads();   // previous tile MMA done (covers Q store on iter 0)
        #pragma unroll
        for (int q = 0; q < 4; q++) {
            *(uint4*)&sKh[row * SMB_STRIDE + seg + q * 4] = kh[q];
            *(uint4*)&sKl[row * SMB_STRIDE + seg + q * 4] = kl[q];
        }
        __syncthreads();

        float acc[4][4][4] = {};
        #pragma unroll
        for (int kc = 0; kc < 4; kc++) {
            uint32_t ah[4][4], al[4][4];
            #pragma unroll
            for (int mt = 0; mt < 4; mt++) {
                int i0 = (wm + mt * 16 + g) * SMB_STRIDE + kc * 8 + cc;
                int i1 = i0 + 8 * SMB_STRIDE;
                ah[mt][0] = sQh[i0];     ah[mt][1] = sQh[i1];
                ah[mt][2] = sQh[i0 + 4]; ah[mt][3] = sQh[i1 + 4];
                al[mt][0] = sQl[i0];     al[mt][1] = sQl[i1];
                al[mt][2] = sQl[i0 + 4]; al[mt][3] = sQl[i1 + 4];
            }
            #pragma unroll
            for (int nt = 0; nt < 4; nt++) {
                int bi = (wn + nt * 8 + g) * SMB_STRIDE + kc * 8 + cc;
                uint32_t bhf[2] = { sKh[bi], sKh[bi + 4] };
                uint32_t blf[2] = { sKl[bi], sKl[bi + 4] };
                #pragma unroll
                for (int mt = 0; mt < 4; mt++) {
                    mma_bf16(acc[mt][nt], ah[mt], bhf);
                    mma_bf16(acc[mt][nt], ah[mt], blf);
                    mma_bf16(acc[mt][nt], al[mt], bhf);
                }
            }
        }

        // epilogue: scale by dist/8, mask, exp, store P, rowsum
        #pragma unroll
        for (int mt = 0; mt < 4; mt++) {
            #pragma unroll
            for (int half = 0; half < 2; half++) {
                int s = s0 + wm + mt * 16 + g + half * 8;
                size_t drow = ((size_t)b * SEQ + s) * SEQ;
                size_t prow = ((size_t)bh * SEQ + s) * SEQ;
                float racc = 0.0f;
                #pragma unroll
                for (int nt = 0; nt < 4; nt++) {
                    int t = t0 + wn + nt * 8 + 2 * cc;
                    float2 sc = make_float2(acc[mt][nt][half * 2],
                                            acc[mt][nt][half * 2 + 1]);
                    float2 d2 = *(const float2*)&dist[drow + t];
                    sc.x *= 0.125f * d2.x;
                    sc.y *= 0.125f * d2.y;
                    bool mk0, mk1;
                    if (kind == 0) {
                        uchar2 mc = *(const uchar2*)&m8[drow + t];
                        mk0 = mc.x; mk1 = mc.y;
                    } else if (kind == 1) {
                        int2 mc = *(const int2*)&mi[drow + t];
                        mk0 = mc.x; mk1 = mc.y;
                    } else {
                        float2 mc = *(const float2*)&mf[drow + t];
                        mk0 = mc.x != 0.0f; mk1 = mc.y != 0.0f;
                    }
                    float2 p;
                    p.x = mk0 ? 0.0f : __expf(sc.x);
                    p.y = mk1 ? 0.0f : __expf(sc.y);
                    *(float2*)&P[prow + t] = p;
                    racc += p.x + p.y;
                }
                rowacc[mt * 2 + half] += racc;
            }
        }
    }

    // reduce over cc lanes, then cross-warp via smem atomics
    #pragma unroll
    for (int r = 0; r < 8; r++) {
        float v = rowacc[r];
        v += __shfl_xor_sync(0xffffffffu, v, 1);
        v += __shfl_xor_sync(0xffffffffu, v, 2);
        if (cc == 0)
            atomicAdd(&srow[wm + (r >> 1) * 16 + g + (r & 1) * 8], v);
    }
    __syncthreads();
    if (tid < 128) rowsum[(size_t)bh * SEQ + s0 + tid] = srow[tid];
}

// ===========================================================================
// HMMA PV: per CTA 128 s x 64 d; t chunked by 64.
// Normalizes P on load (optional writeback); ctx = Pn @ V (V transposed bf16).
// ===========================================================================
#define PV_SMEM ((2 * 128 * SMB_STRIDE + 2 * 64 * SMB_STRIDE) * 4)   // 55296

__global__ void __launch_bounds__(256) attn_pv_hmma_k(
    float* __restrict__ P,
    const __nv_bfloat16* __restrict__ Vthi, const __nv_bfloat16* __restrict__ Vtlo,
    const float* __restrict__ rowsum, float* __restrict__ ctx, int writeback)
{
    extern __shared__ uint32_t sm[];
    uint32_t* sPh = sm;                          // 128*36
    uint32_t* sPl = sPh + 128 * SMB_STRIDE;
    uint32_t* sVh = sPl + 128 * SMB_STRIDE;      // 64*36
    uint32_t* sVl = sVh + 64 * SMB_STRIDE;
    __shared__ float invs[128];

    const int tid = threadIdx.x;
    const int h = blockIdx.x, st = blockIdx.y, b = blockIdx.z;
    const int bh = b * NH + h;
    const int s0 = st * 128;
    const int wid = tid >> 5, lane = tid & 31;
    const int wm = (wid & 3) * 32, wn = (wid >> 2) * 32;
    const int g = lane >> 2, cc = lane & 3;

    if (tid < 128) invs[tid] = 1.0f / rowsum[(size_t)bh * SEQ + s0 + tid];
    __syncthreads();

    const int prow = tid >> 1;                 // s row 0..127
    const int tseg = (tid & 1) * 32;           // t offset within chunk
    const float inv = invs[prow];

    float acc[2][4][4] = {};

    for (int t0 = 0; t0 < SEQ; t0 += 64) {
        // load P 128x64 fp32 (8 float4 per thread)
        float4 p4[8];
        const size_t poff = ((size_t)bh * SEQ + s0 + prow) * SEQ + t0 + tseg;
        #pragma unroll
        for (int q = 0; q < 8; q++) p4[q] = *(const float4*)&P[poff + q * 4];
        // load V 64x64 bf16 (2 x uint4 hi + lo per thread)
        uint4 vh[2], vl[2];
        #pragma unroll
        for (int i = 0; i < 2; i++) {
            int idx = tid + i * 256;
            int vrow = idx >> 3, vq = idx & 7;
            const size_t vo = ((size_t)bh * DH + vrow) * SEQ + t0 + vq * 8;
            vh[i] = *(const uint4*)&Vthi[vo];
            vl[i] = *(const uint4*)&Vtlo[vo];
        }

        __syncthreads();   // previous chunk MMA done

        // normalize, optional writeback, split, store smem
        #pragma unroll
        for (int q = 0; q < 8; q++) {
            p4[q].x *= inv; p4[q].y *= inv; p4[q].z *= inv; p4[q].w *= inv;
        }
        if (writeback) {
            #pragma unroll
            for (int q = 0; q < 8; q++) *(float4*)&P[poff + q * 4] = p4[q];
        }
        #pragma unroll
        for (int q = 0; q < 4; q++) {
            float4 f0 = p4[q * 2], f1 = p4[q * 2 + 1];
            float r0, r1, r2, r3, r4, r5, r6, r7;
            uint4 hi4, lo4;
            hi4.x = pack_hi2(f0.x, f0.y, r0, r1);
            hi4.y = pack_hi2(f0.z, f0.w, r2, r3);
            hi4.z = pack_hi2(f1.x, f1.y, r4, r5);
            hi4.w = pack_hi2(f1.z, f1.w, r6, r7);
            lo4.x = pack_bf2(r0, r1); lo4.y = pack_bf2(r2, r3);
            lo4.z = pack_bf2(r4, r5); lo4.w = pack_bf2(r6, r7);
            int off = prow * SMB_STRIDE + (tseg >> 1) + q * 4;
            *(uint4*)&sPh[off] = hi4;
            *(uint4*)&sPl[off] = lo4;
        }
        #pragma unroll
        for (int i = 0; i < 2; i++) {
            int idx = tid + i * 256;
            int vrow = idx >> 3, vq = idx & 7;
            *(uint4*)&sVh[vrow * SMB_STRIDE + vq * 4] = vh[i];
            *(uint4*)&sVl[vrow * SMB_STRIDE + vq * 4] = vl[i];
        }
        __syncthreads();

        #pragma unroll
        for (int kc = 0; kc < 4; kc++) {
            uint32_t ah[2][4], al[2][4];
            #pragma unroll
            for (int mt = 0; mt < 2; mt++) {
                int i0 = (wm + mt * 16 + g) * SMB_STRIDE + kc * 8 + cc;
                int i1 = i0 + 8 * SMB_STRIDE;
                ah[mt][0] = sPh[i0];     ah[mt][1] = sPh[i1];
                ah[mt][2] = sPh[i0 + 4]; ah[mt][3] = sPh[i1 + 4];
                al[mt][0] = sPl[i0];     al[mt][1] = sPl[i1];
                al[mt][2] = sPl[i0 + 4]; al[mt][3] = sPl[i1 + 4];
            }
            #pragma unroll
            for (int nt = 0; nt < 4; nt++) {
                int bi = (wn + nt * 8 + g) * SMB_STRIDE + kc * 8 + cc;
                uint32_t bhf[2] = { sVh[bi], sVh[bi + 4] };
                uint32_t blf[2] = { sVl[bi], sVl[bi + 4] };
                #pragma unroll
                for (int mt = 0; mt < 2; mt++) {
                    mma_bf16(acc[mt][nt], ah[mt], bhf);
                    mma_bf16(acc[mt][nt], ah[mt], blf);
                    mma_bf16(acc[mt][nt], al[mt], bhf);
                }
            }
        }
    }

    // epilogue: ctx [b,h,s,d] fp32
    #pragma unroll
    for (int mt = 0; mt < 2; mt++) {
        #pragma unroll
        for (int half = 0; half < 2; half++) {
            int s = s0 + wm + mt * 16 + g + half * 8;
            #pragma unroll
            for (int nt = 0; nt < 4; nt++) {
                int d = wn + nt * 8 + 2 * cc;
                float2 v = make_float2(acc[mt][nt][half * 2],
                                       acc[mt][nt][half * 2 + 1]);
                *(float2*)&ctx[((size_t)bh * SEQ + s) * DH + d] = v;
            }
        }
    }
}

// ===========================================================================
// Launch
// ===========================================================================
extern "C" void kernel_launch(void* const* d_in, const int* in_sizes, int n_in,
                              void* d_out, int out_size)
{
    const float* inQ   = (const float*)d_in[0];
    const float* inK   = (const float*)d_in[1];
    const float* inV   = (const float*)d_in[2];
    const float* inter = (const float*)d_in[3];
    const float* dist  = (const float*)d_in[4];
    const void*  mask  = d_in[5];
    const float* W_Q   = (const float*)d_in[6];
    const float* W_K   = (const float*)d_in[7];
    const float* W_V   = (const float*)d_in[8];
    const float* W_fc  = (const float*)d_in[9];
    const float* We_w  = (const float*)d_in[10];
    const float* We_b  = (const float*)d_in[11];
    float* out = (float*)d_out;

    void *coefp_, *ctxp_, *rsp_, *pbuf_, *whi_, *wlo_;
    void *qhi_, *qlo_, *khi_, *klo_, *vthi_, *vtlo_;
    cudaGetSymbolAddress(&coefp_, g_coef);
    cudaGetSymbolAddress(&ctxp_,  g_ctx);
    cudaGetSymbolAddress(&rsp_,   g_rowsum);
    cudaGetSymbolAddress(&pbuf_,  g_Pbuf);
    cudaGetSymbolAddress(&whi_,   g_Whi);
    cudaGetSymbolAddress(&wlo_,   g_Wlo);
    cudaGetSymbolAddress(&qhi_,   g_Qhi);
    cudaGetSymbolAddress(&qlo_,   g_Qlo);
    cudaGetSymbolAddress(&khi_,   g_Khi);
    cudaGetSymbolAddress(&klo_,   g_Klo);
    cudaGetSymbolAddress(&vthi_,  g_Vthi);
    cudaGetSymbolAddress(&vtlo_,  g_Vtlo);
    float* coefp = (float*)coefp_;
    float* ctxp  = (float*)ctxp_;
    float* rsp   = (float*)rsp_;
    __nv_bfloat16* Whi  = (__nv_bfloat16*)whi_;
    __nv_bfloat16* Wlo  = (__nv_bfloat16*)wlo_;
    __nv_bfloat16* Qhi  = (__nv_bfloat16*)qhi_;
    __nv_bfloat16* Qlo  = (__nv_bfloat16*)qlo_;
    __nv_bfloat16* Khi  = (__nv_bfloat16*)khi_;
    __nv_bfloat16* Klo  = (__nv_bfloat16*)klo_;
    __nv_bfloat16* Vthi = (__nv_bfloat16*)vthi_;
    __nv_bfloat16* Vtlo = (__nv_bfloat16*)vtlo_;
    const size_t WSZ = (size_t)DMODEL * DMODEL;

    const bool need_attn = ((size_t)out_size >= OUT_ELEMS + ATTN_ELEMS);
    float* P = need_attn ? (out + OUT_ELEMS) : (float*)pbuf_;

    cudaFuncSetAttribute(gemm_hmma_k<0>, cudaFuncAttributeMaxDynamicSharedMemorySize, SM_TOTAL);
    cudaFuncSetAttribute(gemm_hmma_k<1>, cudaFuncAttributeMaxDynamicSharedMemorySize, SM_TOTAL);
    cudaFuncSetAttribute(gemm_hmma_k<2>, cudaFuncAttributeMaxDynamicSharedMemorySize, SM_TOTAL);
    cudaFuncSetAttribute(gemm_hmma_k<3>, cudaFuncAttributeMaxDynamicSharedMemorySize, SM_TOTAL);
    cudaFuncSetAttribute(attn_scores_hmma_k, cudaFuncAttributeMaxDynamicSharedMemorySize, SC_SMEM);
    cudaFuncSetAttribute(attn_pv_hmma_k,     cudaFuncAttributeMaxDynamicSharedMemorySize, PV_SMEM);

    dim3 thr(256);
    dim3 wgrid(DMODEL / 32, DMODEL / 32);        // (32, 32)
    dim3 ggrid(DMODEL / 128, MTOT / 128);        // (8, 32)
    dim3 agrid(NH, SEQ / 128, BB);               // (16, 16, 2)

    detect_mask_kind_k<<<1, 256>>>((const unsigned char*)mask);

    wconv_k<<<wgrid, thr>>>(We_w, Whi + 0 * WSZ, Wlo + 0 * WSZ);
    wconv_k<<<wgrid, thr>>>(W_Q,  Whi + 1 * WSZ, Wlo + 1 * WSZ);
    wconv_k<<<wgrid, thr>>>(W_K,  Whi + 2 * WSZ, Wlo + 2 * WSZ);
    wconv_k<<<wgrid, thr>>>(W_V,  Whi + 3 * WSZ, Wlo + 3 * WSZ);
    wconv_k<<<wgrid, thr>>>(W_fc, Whi + 4 * WSZ, Wlo + 4 * WSZ);

    gemm_hmma_k<0><<<ggrid, thr, SM_TOTAL>>>(inter, Whi + 0 * WSZ, Wlo + 0 * WSZ, We_b, coefp, nullptr, nullptr);
    gemm_hmma_k<1><<<ggrid, thr, SM_TOTAL>>>(inQ,   Whi + 1 * WSZ, Wlo + 1 * WSZ, coefp, nullptr, Qhi, Qlo);
    gemm_hmma_k<1><<<ggrid, thr, SM_TOTAL>>>(inK,   Whi + 2 * WSZ, Wlo + 2 * WSZ, coefp, nullptr, Khi, Klo);
    gemm_hmma_k<2><<<ggrid, thr, SM_TOTAL>>>(inV,   Whi + 3 * WSZ, Wlo + 3 * WSZ, nullptr, nullptr, Vthi, Vtlo);

    attn_scores_hmma_k<<<agrid, thr, SC_SMEM>>>(Qhi, Qlo, Khi, Klo, dist, mask, P, rsp);
    attn_pv_hmma_k<<<agrid, thr, PV_SMEM>>>(P, Vthi, Vtlo, rsp, ctxp, need_attn ? 1 : 0);

    gemm_hmma_k<3><<<ggrid, thr, SM_TOTAL>>>(ctxp, Whi + 4 * WSZ, Wlo + 4 * WSZ, inQ, out, nullptr, nullptr);
}

// round 17
// speedup vs baseline: 1.0658x; 1.0658x over previous
#include <cuda_runtime.h>
#include <cuda_bf16.h>
#include <math.h>
#include <stdint.h>

// Problem constants
#define BB   2
#define SEQ  2048
#define DMODEL 1024
#define NH   16
#define DH   64
#define BH   (BB*NH)          // 32
#define MTOT (BB*SEQ)         // 4096

#define OUT_ELEMS  ((size_t)MTOT * DMODEL)          // 4,194,304
#define ATTN_ELEMS ((size_t)BH * SEQ * SEQ)         // 134,217,728

typedef unsigned long long u64;

// ===========================================================================
// HMMA m16n8k16 bf16 (portable PTX). Fragment layout (verified R15/R16):
//   A row-major 16x16: a0=A[g][2cc..+1] a1=A[g+8][..] a2=A[g][2cc+8..] a3=A[g+8][..]
//   B col-major 16x8 stored smem[n][k]: b0=B[n=g][2cc..+1] b1=B[n=g][2cc+8..]
//   C: c0,c1=C[g][2cc..+1]; c2,c3=C[g+8][2cc..+1]
// ===========================================================================
__device__ __forceinline__ void mma_bf16(float* c, const uint32_t* a, const uint32_t* b) {
    asm volatile(
        "mma.sync.aligned.m16n8k16.row.col.f32.bf16.bf16.f32 "
        "{%0,%1,%2,%3}, {%4,%5,%6,%7}, {%8,%9}, {%0,%1,%2,%3};"
        : "+f"(c[0]), "+f"(c[1]), "+f"(c[2]), "+f"(c[3])
        : "r"(a[0]), "r"(a[1]), "r"(a[2]), "r"(a[3]), "r"(b[0]), "r"(b[1]));
}

__device__ __forceinline__ uint32_t pack_hi2(float a, float b, float& ra, float& rb) {
    __nv_bfloat16 ha = __float2bfloat16(a), hb = __float2bfloat16(b);
    ra = a - __bfloat162float(ha); rb = b - __bfloat162float(hb);
    __nv_bfloat162 p = __halves2bfloat162(ha, hb);
    return *reinterpret_cast<uint32_t*>(&p);
}
__device__ __forceinline__ uint32_t pack_bf2(float a, float b) {
    __nv_bfloat162 p = __floats2bfloat162_rn(a, b);
    return *reinterpret_cast<uint32_t*>(&p);
}

// ===========================================================================
// Scratch
// ===========================================================================
__device__ float g_coef[MTOT * DMODEL];
__device__ __nv_bfloat16 g_Qhi[BH * SEQ * DH];   // [b,h,s,d]
__device__ __nv_bfloat16 g_Qlo[BH * SEQ * DH];
__device__ __nv_bfloat16 g_Khi[BH * SEQ * DH];   // [b,h,s,d]
__device__ __nv_bfloat16 g_Klo[BH * SEQ * DH];
__device__ __nv_bfloat16 g_Vthi[BH * DH * SEQ];  // [b,h,d,s]  (transposed)
__device__ __nv_bfloat16 g_Vtlo[BH * DH * SEQ];
__device__ float g_ctx[BH * SEQ * DH];
__device__ float g_rowsum[BH * SEQ];
__device__ int   g_mask_kind;   // 0=u8, 1=i32, 2=f32
__device__ __nv_bfloat16 g_Whi[5 * DMODEL * DMODEL];
__device__ __nv_bfloat16 g_Wlo[5 * DMODEL * DMODEL];

// ===========================================================================
// Mask dtype detector
// ===========================================================================
__global__ void detect_mask_kind_k(const unsigned char* __restrict__ m) {
    __shared__ int odd1, f3;
    if (threadIdx.x == 0) { odd1 = 0; f3 = 0; }
    __syncthreads();
    int lo = 0, lf = 0;
    for (int i = threadIdx.x; i < 4096; i += blockDim.x) {
        unsigned char b = m[i];
        if ((i & 3) != 0 && b == 1)    lo = 1;
        if ((i & 3) == 3 && b == 0x3F) lf = 1;
    }
    if (lo) atomicOr(&odd1, 1);
    if (lf) atomicOr(&f3, 1);
    __syncthreads();
    if (threadIdx.x == 0) g_mask_kind = odd1 ? 0 : (f3 ? 2 : 1);
}

// ===========================================================================
// Weight prep: transpose fp32 W [K,N] -> bf16 hi/lo [N,K]
// ===========================================================================
__global__ void __launch_bounds__(256) wconv_k(
    const float* __restrict__ W,
    __nv_bfloat16* __restrict__ hiT, __nv_bfloat16* __restrict__ loT)
{
    __shared__ float t[32][33];
    const int n0 = blockIdx.x * 32, k0 = blockIdx.y * 32;
    const int tx = threadIdx.x & 31, ty = threadIdx.x >> 5;
    #pragma unroll
    for (int i = 0; i < 4; i++) {
        int kk = ty + i * 8;
        t[kk][tx] = W[(size_t)(k0 + kk) * DMODEL + n0 + tx];
    }
    __syncthreads();
    #pragma unroll
    for (int i = 0; i < 4; i++) {
        int nn = ty + i * 8;
        float x = t[tx][nn];
        __nv_bfloat16 h = __float2bfloat16(x);
        float r = x - __bfloat162float(h);
        size_t o = (size_t)(n0 + nn) * DMODEL + k0 + tx;
        hiT[o] = h;
        loT[o] = __float2bfloat16(r);
    }
}

// ===========================================================================
// HMMA bf16-split GEMM (unchanged core from passing R15/R16)
// MODE 0: coef = 1 + sigmoid(A@W + bias)            -> C fp32 [m][n]
// MODE 1: (A@W) * coef                              -> Chi/Clo bf16 [b,h,s,d]
// MODE 2: plain projection                          -> Chi/Clo bf16 [b,h,d,s]
// MODE 3: A from [b,h,s,d]; C = A@W + residual      -> C fp32 [m][n]
// ===========================================================================
#define SMB_STRIDE 36
#define SM_ARR (128 * SMB_STRIDE)
#define SM_TOTAL (4 * SM_ARR * 4)   // 73728 bytes

template<int MODE>
__global__ void __launch_bounds__(256) gemm_hmma_k(
    const float* __restrict__ A,
    const __nv_bfloat16* __restrict__ BhiT, const __nv_bfloat16* __restrict__ BloT,
    const float* __restrict__ aux, float* __restrict__ C,
    __nv_bfloat16* __restrict__ Chi, __nv_bfloat16* __restrict__ Clo)
{
    extern __shared__ uint32_t sm[];
    uint32_t* sAhi = sm;
    uint32_t* sAlo = sAhi + SM_ARR;
    uint32_t* sBhi = sAlo + SM_ARR;
    uint32_t* sBlo = sBhi + SM_ARR;

    const int tid = threadIdx.x;
    const int m0 = blockIdx.y * 128, n0 = blockIdx.x * 128;
    const int wid = tid >> 5, lane = tid & 31;
    const int wm = (wid & 1) * 64, wn = (wid >> 1) * 32;
    const int g = lane >> 2, cc = lane & 3;

    const int row  = tid >> 1;
    const int kseg = (tid & 1) * 32;

    float acc[4][4][4] = {};

    for (int ch = 0; ch < 16; ch++) {
        const int k0 = ch * 64;

        float4 a[8];
        if (MODE == 3) {
            int m = m0 + row;
            int b = m >> 11, s = m & (SEQ - 1);
            int h = k0 >> 6;
            const float* src = &A[(((size_t)(b * NH + h)) * SEQ + s) * DH + kseg];
            #pragma unroll
            for (int q = 0; q < 8; q++) a[q] = *(const float4*)&src[q * 4];
        } else {
            const float* src = &A[(size_t)(m0 + row) * DMODEL + k0 + kseg];
            #pragma unroll
            for (int q = 0; q < 8; q++) a[q] = *(const float4*)&src[q * 4];
        }
        uint4 bh4[4], bl4[4];
        {
            const size_t bo = (size_t)(n0 + row) * DMODEL + k0 + kseg;
            #pragma unroll
            for (int q = 0; q < 4; q++) {
                bh4[q] = *(const uint4*)&BhiT[bo + q * 8];
                bl4[q] = *(const uint4*)&BloT[bo + q * 8];
            }
        }

        __syncthreads();

        #pragma unroll
        for (int q = 0; q < 4; q++) {
            float4 f0 = a[q * 2], f1 = a[q * 2 + 1];
            float r0, r1, r2, r3, r4, r5, r6, r7;
            uint4 hi4, lo4;
            hi4.x = pack_hi2(f0.x, f0.y, r0, r1);
            hi4.y = pack_hi2(f0.z, f0.w, r2, r3);
            hi4.z = pack_hi2(f1.x, f1.y, r4, r5);
            hi4.w = pack_hi2(f1.z, f1.w, r6, r7);
            lo4.x = pack_bf2(r0, r1); lo4.y = pack_bf2(r2, r3);
            lo4.z = pack_bf2(r4, r5); lo4.w = pack_bf2(r6, r7);
            int off = row * SMB_STRIDE + (kseg >> 1) + q * 4;
            *(uint4*)&sAhi[off] = hi4;
            *(uint4*)&sAlo[off] = lo4;
            *(uint4*)&sBhi[off] = bh4[q];
            *(uint4*)&sBlo[off] = bl4[q];
        }
        __syncthreads();

        #pragma unroll
        for (int kc = 0; kc < 4; kc++) {
            uint32_t ah[4][4], al[4][4];
            #pragma unroll
            for (int mt = 0; mt < 4; mt++) {
                int i0 = (wm + mt * 16 + g) * SMB_STRIDE + kc * 8 + cc;
                int i1 = i0 + 8 * SMB_STRIDE;
                ah[mt][0] = sAhi[i0];     ah[mt][1] = sAhi[i1];
                ah[mt][2] = sAhi[i0 + 4]; ah[mt][3] = sAhi[i1 + 4];
                al[mt][0] = sAlo[i0];     al[mt][1] = sAlo[i1];
                al[mt][2] = sAlo[i0 + 4]; al[mt][3] = sAlo[i1 + 4];
            }
            #pragma unroll
            for (int nt = 0; nt < 4; nt++) {
                int bi = (wn + nt * 8 + g) * SMB_STRIDE + kc * 8 + cc;
                uint32_t bh[2] = { sBhi[bi], sBhi[bi + 4] };
                uint32_t bl[2] = { sBlo[bi], sBlo[bi + 4] };
                #pragma unroll
                for (int mt = 0; mt < 4; mt++) {
                    mma_bf16(acc[mt][nt], ah[mt], bh);
                    mma_bf16(acc[mt][nt], ah[mt], bl);
                    mma_bf16(acc[mt][nt], al[mt], bh);
                }
            }
        }
    }

    auto epi = [&](int m, int n, float2 v) {
        if (MODE == 0) {
            float2 bb = *(const float2*)&aux[n];
            v.x = 1.0f + 1.0f / (1.0f + __expf(-(v.x + bb.x)));
            v.y = 1.0f + 1.0f / (1.0f + __expf(-(v.y + bb.y)));
            *(float2*)&C[(size_t)m * DMODEL + n] = v;
        } else if (MODE == 1) {
            float2 cf = *(const float2*)&aux[(size_t)m * DMODEL + n];
            v.x *= cf.x; v.y *= cf.y;
            int b = m >> 11, s = m & (SEQ - 1);
            int h = n >> 6, d = n & 63;
            float r0, r1;
            uint32_t hi = pack_hi2(v.x, v.y, r0, r1);
            uint32_t lo = pack_bf2(r0, r1);
            size_t o = (((size_t)(b * NH + h)) * SEQ + s) * DH + d;
            *(uint32_t*)&Chi[o] = hi;
            *(uint32_t*)&Clo[o] = lo;
        } else if (MODE == 2) {
            int b = m >> 11, s = m & (SEQ - 1);
            int h = n >> 6, d = n & 63;
            size_t o0 = (((size_t)(b * NH + h)) * DH + d) * SEQ + s;
            __nv_bfloat16 h0 = __float2bfloat16(v.x);
            __nv_bfloat16 h1 = __float2bfloat16(v.y);
            Chi[o0]       = h0;
            Chi[o0 + SEQ] = h1;
            Clo[o0]       = __float2bfloat16(v.x - __bfloat162float(h0));
            Clo[o0 + SEQ] = __float2bfloat16(v.y - __bfloat162float(h1));
        } else {
            float2 r = *(const float2*)&aux[(size_t)m * DMODEL + n];
            v.x += r.x; v.y += r.y;
            *(float2*)&C[(size_t)m * DMODEL + n] = v;
        }
    };

    #pragma unroll
    for (int mt = 0; mt < 4; mt++) {
        #pragma unroll
        for (int nt = 0; nt < 4; nt++) {
            int m = m0 + wm + mt * 16 + g;
            int n = n0 + wn + nt * 8 + 2 * cc;
            epi(m,     n, make_float2(acc[mt][nt][0], acc[mt][nt][1]));
            epi(m + 8, n, make_float2(acc[mt][nt][2], acc[mt][nt][3]));
        }
    }
}

// ===========================================================================
// FUSED attention: per CTA 128 s-rows, loop over t tiles of 128.
// scores MMA -> exp (+P gmem store if needed) -> P tile to smem bf16 hi/lo
// -> PV MMA accumulates ctx in registers. Rowsum + normalized ctx at end.
// ===========================================================================
#define STRQ 36
#define STRP 68
#define FU_QH 0
#define FU_QL (FU_QH + 128*STRQ)
#define FU_KH (FU_QL + 128*STRQ)
#define FU_KL (FU_KH + 128*STRQ)
#define FU_PH (FU_KL + 128*STRQ)
#define FU_PL (FU_PH + 128*STRP)
#define FU_VH (FU_PL + 128*STRP)
#define FU_VL (FU_VH + 64*STRP)
#define FU_SMEM ((FU_VL + 64*STRP) * 4)   // 178176 bytes

__global__ void __launch_bounds__(256) attn_fused_k(
    const __nv_bfloat16* __restrict__ Qhi, const __nv_bfloat16* __restrict__ Qlo,
    const __nv_bfloat16* __restrict__ Khi, const __nv_bfloat16* __restrict__ Klo,
    const __nv_bfloat16* __restrict__ Vthi, const __nv_bfloat16* __restrict__ Vtlo,
    const float* __restrict__ dist, const void* __restrict__ mask,
    float* __restrict__ P, float* __restrict__ rowsum, float* __restrict__ ctx,
    int store_p)
{
    extern __shared__ uint32_t sm[];
    uint32_t* sQh = sm + FU_QH;
    uint32_t* sQl = sm + FU_QL;
    uint32_t* sKh = sm + FU_KH;
    uint32_t* sKl = sm + FU_KL;
    uint32_t* sPh = sm + FU_PH;
    uint32_t* sPl = sm + FU_PL;
    uint32_t* sVh = sm + FU_VH;
    uint32_t* sVl = sm + FU_VL;
    __shared__ float srow[128];

    const int tid = threadIdx.x;
    const int h = blockIdx.x, st = blockIdx.y, b = blockIdx.z;
    const int bh = b * NH + h;
    const int s0 = st * 128;
    const int kind = g_mask_kind;
    const int wid = tid >> 5, lane = tid & 31;
    const int g = lane >> 2, cc = lane & 3;
    // scores warp tiling: 2m x 4n over 128x128
    const int wmS = (wid & 1) * 64, wnS = (wid >> 1) * 32;
    // PV warp tiling: 4m x 2n over 128x64
    const int wmP = (wid & 3) * 32, wnP = (wid >> 2) * 32;

    if (tid < 128) srow[tid] = 0.0f;

    // Q tile once (2 threads per row)
    {
        const int row = tid >> 1, seg = (tid & 1) * 16;
        const size_t qo = ((size_t)bh * SEQ + s0 + row) * DH + (tid & 1) * 32;
        const uint4* qh = (const uint4*)&Qhi[qo];
        const uint4* ql = (const uint4*)&Qlo[qo];
        #pragma unroll
        for (int q = 0; q < 4; q++) {
            *(uint4*)&sQh[row * STRQ + seg + q * 4] = qh[q];
            *(uint4*)&sQl[row * STRQ + seg + q * 4] = ql[q];
        }
    }

    float rowacc[8] = {};
    float cacc[2][4][4] = {};

    const unsigned char* m8 = (const unsigned char*)mask;
    const int*           mi = (const int*)mask;
    const float*         mf = (const float*)mask;

    for (int t0 = 0; t0 < SEQ; t0 += 128) {
        // --- 1. load K + V tiles to regs ---
        const int krow = tid >> 1, kseg = (tid & 1) * 16;
        uint4 kh[4], kl[4];
        {
            const size_t ko = ((size_t)bh * SEQ + t0 + krow) * DH + (tid & 1) * 32;
            const uint4* khp = (const uint4*)&Khi[ko];
            const uint4* klp = (const uint4*)&Klo[ko];
            #pragma unroll
            for (int q = 0; q < 4; q++) { kh[q] = khp[q]; kl[q] = klp[q]; }
        }
        const int vrow = tid >> 2, vseg = (tid & 3) * 16;
        uint4 vh[4], vl[4];
        {
            const size_t vo = ((size_t)bh * DH + vrow) * SEQ + t0 + (tid & 3) * 32;
            const uint4* vhp = (const uint4*)&Vthi[vo];
            const uint4* vlp = (const uint4*)&Vtlo[vo];
            #pragma unroll
            for (int q = 0; q < 4; q++) { vh[q] = vhp[q]; vl[q] = vlp[q]; }
        }

        __syncthreads();   // prev PV MMA done reading sP/sV (and Q store iter0)

        #pragma unroll
        for (int q = 0; q < 4; q++) {
            *(uint4*)&sKh[krow * STRQ + kseg + q * 4] = kh[q];
            *(uint4*)&sKl[krow * STRQ + kseg + q * 4] = kl[q];
            *(uint4*)&sVh[vrow * STRP + vseg + q * 4] = vh[q];
            *(uint4*)&sVl[vrow * STRP + vseg + q * 4] = vl[q];
        }
        __syncthreads();

        // --- scores MMA: 128x128, K-dim 64 ---
        float acc[4][4][4] = {};
        #pragma unroll
        for (int kc = 0; kc < 4; kc++) {
            uint32_t ah[4][4], al[4][4];
            #pragma unroll
            for (int mt = 0; mt < 4; mt++) {
                int i0 = (wmS + mt * 16 + g) * STRQ + kc * 8 + cc;
                int i1 = i0 + 8 * STRQ;
                ah[mt][0] = sQh[i0];     ah[mt][1] = sQh[i1];
                ah[mt][2] = sQh[i0 + 4]; ah[mt][3] = sQh[i1 + 4];
                al[mt][0] = sQl[i0];     al[mt][1] = sQl[i1];
                al[mt][2] = sQl[i0 + 4]; al[mt][3] = sQl[i1 + 4];
            }
            #pragma unroll
            for (int nt = 0; nt < 4; nt++) {
                int bi = (wnS + nt * 8 + g) * STRQ + kc * 8 + cc;
                uint32_t bhf[2] = { sKh[bi], sKh[bi + 4] };
                uint32_t blf[2] = { sKl[bi], sKl[bi + 4] };
                #pragma unroll
                for (int mt = 0; mt < 4; mt++) {
                    mma_bf16(acc[mt][nt], ah[mt], bhf);
                    mma_bf16(acc[mt][nt], ah[mt], blf);
                    mma_bf16(acc[mt][nt], al[mt], bhf);
                }
            }
        }

        // --- epilogue: dist*scale, mask, exp, (P gmem), P tile -> smem ---
        #pragma unroll
        for (int mt = 0; mt < 4; mt++) {
            #pragma unroll
            for (int half = 0; half < 2; half++) {
                int sl = wmS + mt * 16 + g + half * 8;
                int s = s0 + sl;
                size_t drow = ((size_t)b * SEQ + s) * SEQ;
                size_t prow = ((size_t)bh * SEQ + s) * SEQ;
                float racc = 0.0f;
                #pragma unroll
                for (int nt = 0; nt < 4; nt++) {
                    int t = t0 + wnS + nt * 8 + 2 * cc;
                    float2 sc = make_float2(acc[mt][nt][half * 2],
                                            acc[mt][nt][half * 2 + 1]);
                    float2 d2 = *(const float2*)&dist[drow + t];
                    sc.x *= 0.125f * d2.x;
                    sc.y *= 0.125f * d2.y;
                    bool mk0, mk1;
                    if (kind == 0) {
                        uchar2 mc = *(const uchar2*)&m8[drow + t];
                        mk0 = mc.x; mk1 = mc.y;
                    } else if (kind == 1) {
                        int2 mc = *(const int2*)&mi[drow + t];
                        mk0 = mc.x; mk1 = mc.y;
                    } else {
                        float2 mc = *(const float2*)&mf[drow + t];
                        mk0 = mc.x != 0.0f; mk1 = mc.y != 0.0f;
                    }
                    float2 p;
                    p.x = mk0 ? 0.0f : __expf(sc.x);
                    p.y = mk1 ? 0.0f : __expf(sc.y);
                    if (store_p) *(float2*)&P[prow + t] = p;
                    racc += p.x + p.y;
                    float r0, r1;
                    uint32_t hi = pack_hi2(p.x, p.y, r0, r1);
                    uint32_t lo = pack_bf2(r0, r1);
                    int idx = sl * STRP + ((wnS + nt * 8) >> 1) + cc;
                    sPh[idx] = hi;
                    sPl[idx] = lo;
                }
                rowacc[mt * 2 + half] += racc;
            }
        }
        __syncthreads();

        // --- PV MMA: ctx(128x64) += P(128x128) @ V(128x64), k-dim = t(128) ---
        #pragma unroll
        for (int kc = 0; kc < 8; kc++) {
            uint32_t ah[2][4], al[2][4];
            #pragma unroll
            for (int mt = 0; mt < 2; mt++) {
                int i0 = (wmP + mt * 16 + g) * STRP + kc * 8 + cc;
                int i1 = i0 + 8 * STRP;
                ah[mt][0] = sPh[i0];     ah[mt][1] = sPh[i1];
                ah[mt][2] = sPh[i0 + 4]; ah[mt][3] = sPh[i1 + 4];
                al[mt][0] = sPl[i0];     al[mt][1] = sPl[i1];
                al[mt][2] = sPl[i0 + 4]; al[mt][3] = sPl[i1 + 4];
            }
            #pragma unroll
            for (int nt = 0; nt < 4; nt++) {
                int bi = (wnP + nt * 8 + g) * STRP + kc * 8 + cc;
                uint32_t bhf[2] = { sVh[bi], sVh[bi + 4] };
                uint32_t blf[2] = { sVl[bi], sVl[bi + 4] };
                #pragma unroll
                for (int mt = 0; mt < 2; mt++) {
                    mma_bf16(cacc[mt][nt], ah[mt], bhf);
                    mma_bf16(cacc[mt][nt], ah[mt], blf);
                    mma_bf16(cacc[mt][nt], al[mt], bhf);
                }
            }
        }
    }

    // --- rowsum reduce (scores lane mapping) ---
    #pragma unroll
    for (int r = 0; r < 8; r++) {
        float v = rowacc[r];
        v += __shfl_xor_sync(0xffffffffu, v, 1);
        v += __shfl_xor_sync(0xffffffffu, v, 2);
        if (cc == 0)
            atomicAdd(&srow[wmS + (r >> 1) * 16 + g + (r & 1) * 8], v);
    }
    __syncthreads();
    if (tid < 128) rowsum[(size_t)bh * SEQ + s0 + tid] = srow[tid];

    // --- ctx write, normalized in-kernel ---
    #pragma unroll
    for (int mt = 0; mt < 2; mt++) {
        #pragma unroll
        for (int half = 0; half < 2; half++) {
            int sl = wmP + mt * 16 + g + half * 8;
            float inv = 1.0f / srow[sl];
            int s = s0 + sl;
            #pragma unroll
            for (int nt = 0; nt < 4; nt++) {
                int d = wnP + nt * 8 + 2 * cc;
                float2 v = make_float2(cacc[mt][nt][half * 2] * inv,
                                       cacc[mt][nt][half * 2 + 1] * inv);
                *(float2*)&ctx[((size_t)bh * SEQ + s) * DH + d] = v;
            }
        }
    }
}

// ===========================================================================
// Normalize P in place: one block per row, 2 float4 per thread.
// ===========================================================================
__global__ void __launch_bounds__(256) norm_p_k(
    float* __restrict__ P, const float* __restrict__ rowsum)
{
    const int row = blockIdx.x;
    const float inv = 1.0f / rowsum[row];
    float4* p = (float4*)(P + (size_t)row * SEQ);
    const int t = threadIdx.x;
    float4 a = p[t], b = p[t + 256];
    a.x *= inv; a.y *= inv; a.z *= inv; a.w *= inv;
    b.x *= inv; b.y *= inv; b.z *= inv; b.w *= inv;
    p[t] = a; p[t + 256] = b;
}

// ===========================================================================
// Launch
// ===========================================================================
extern "C" void kernel_launch(void* const* d_in, const int* in_sizes, int n_in,
                              void* d_out, int out_size)
{
    const float* inQ   = (const float*)d_in[0];
    const float* inK   = (const float*)d_in[1];
    const float* inV   = (const float*)d_in[2];
    const float* inter = (const float*)d_in[3];
    const float* dist  = (const float*)d_in[4];
    const void*  mask  = d_in[5];
    const float* W_Q   = (const float*)d_in[6];
    const float* W_K   = (const float*)d_in[7];
    const float* W_V   = (const float*)d_in[8];
    const float* W_fc  = (const float*)d_in[9];
    const float* We_w  = (const float*)d_in[10];
    const float* We_b  = (const float*)d_in[11];
    float* out = (float*)d_out;

    void *coefp_, *ctxp_, *rsp_, *whi_, *wlo_;
    void *qhi_, *qlo_, *khi_, *klo_, *vthi_, *vtlo_;
    cudaGetSymbolAddress(&coefp_, g_coef);
    cudaGetSymbolAddress(&ctxp_,  g_ctx);
    cudaGetSymbolAddress(&rsp_,   g_rowsum);
    cudaGetSymbolAddress(&whi_,   g_Whi);
    cudaGetSymbolAddress(&wlo_,   g_Wlo);
    cudaGetSymbolAddress(&qhi_,   g_Qhi);
    cudaGetSymbolAddress(&qlo_,   g_Qlo);
    cudaGetSymbolAddress(&khi_,   g_Khi);
    cudaGetSymbolAddress(&klo_,   g_Klo);
    cudaGetSymbolAddress(&vthi_,  g_Vthi);
    cudaGetSymbolAddress(&vtlo_,  g_Vtlo);
    float* coefp = (float*)coefp_;
    float* ctxp  = (float*)ctxp_;
    float* rsp   = (float*)rsp_;
    __nv_bfloat16* Whi  = (__nv_bfloat16*)whi_;
    __nv_bfloat16* Wlo  = (__nv_bfloat16*)wlo_;
    __nv_bfloat16* Qhi  = (__nv_bfloat16*)qhi_;
    __nv_bfloat16* Qlo  = (__nv_bfloat16*)qlo_;
    __nv_bfloat16* Khi  = (__nv_bfloat16*)khi_;
    __nv_bfloat16* Klo  = (__nv_bfloat16*)klo_;
    __nv_bfloat16* Vthi = (__nv_bfloat16*)vthi_;
    __nv_bfloat16* Vtlo = (__nv_bfloat16*)vtlo_;
    const size_t WSZ = (size_t)DMODEL * DMODEL;

    const bool need_attn = ((size_t)out_size >= OUT_ELEMS + ATTN_ELEMS);
    float* P = need_attn ? (out + OUT_ELEMS) : nullptr;

    cudaFuncSetAttribute(gemm_hmma_k<0>, cudaFuncAttributeMaxDynamicSharedMemorySize, SM_TOTAL);
    cudaFuncSetAttribute(gemm_hmma_k<1>, cudaFuncAttributeMaxDynamicSharedMemorySize, SM_TOTAL);
    cudaFuncSetAttribute(gemm_hmma_k<2>, cudaFuncAttributeMaxDynamicSharedMemorySize, SM_TOTAL);
    cudaFuncSetAttribute(gemm_hmma_k<3>, cudaFuncAttributeMaxDynamicSharedMemorySize, SM_TOTAL);
    cudaFuncSetAttribute(attn_fused_k,   cudaFuncAttributeMaxDynamicSharedMemorySize, FU_SMEM);

    dim3 thr(256);
    dim3 wgrid(DMODEL / 32, DMODEL / 32);        // (32, 32)
    dim3 ggrid(DMODEL / 128, MTOT / 128);        // (8, 32)
    dim3 agrid(NH, SEQ / 128, BB);               // (16, 16, 2)

    detect_mask_kind_k<<<1, 256>>>((const unsigned char*)mask);

    wconv_k<<<wgrid, thr>>>(We_w, Whi + 0 * WSZ, Wlo + 0 * WSZ);
    wconv_k<<<wgrid, thr>>>(W_Q,  Whi + 1 * WSZ, Wlo + 1 * WSZ);
    wconv_k<<<wgrid, thr>>>(W_K,  Whi + 2 * WSZ, Wlo + 2 * WSZ);
    wconv_k<<<wgrid, thr>>>(W_V,  Whi + 3 * WSZ, Wlo + 3 * WSZ);
    wconv_k<<<wgrid, thr>>>(W_fc, Whi + 4 * WSZ, Wlo + 4 * WSZ);

    gemm_hmma_k<0><<<ggrid, thr, SM_TOTAL>>>(inter, Whi + 0 * WSZ, Wlo + 0 * WSZ, We_b, coefp, nullptr, nullptr);
    gemm_hmma_k<1><<<ggrid, thr, SM_TOTAL>>>(inQ,   Whi + 1 * WSZ, Wlo + 1 * WSZ, coefp, nullptr, Qhi, Qlo);
    gemm_hmma_k<1><<<ggrid, thr, SM_TOTAL>>>(inK,   Whi + 2 * WSZ, Wlo + 2 * WSZ, coefp, nullptr, Khi, Klo);
    gemm_hmma_k<2><<<ggrid, thr, SM_TOTAL>>>(inV,   Whi + 3 * WSZ, Wlo + 3 * WSZ, nullptr, nullptr, Vthi, Vtlo);

    attn_fused_k<<<agrid, thr, FU_SMEM>>>(Qhi, Qlo, Khi, Klo, Vthi, Vtlo,
                                          dist, mask, P, rsp, ctxp,
                                          need_attn ? 1 : 0);
    if (need_attn)
        norm_p_k<<<BH * SEQ, 256>>>(P, rsp);

    gemm_hmma_k<3><<<ggrid, thr, SM_TOTAL>>>(ctxp, Whi + 4 * WSZ, Wlo + 4 * WSZ, inQ, out, nullptr, nullptr);
}